// round 9
// baseline (speedup 1.0000x reference)
#include <cuda_runtime.h>

#define BATCH 128
#define SITES 256
#define BOND 64
#define NOUT 10
#define HALFS 128            // sites per half
#define NPAIRS 64            // site pairs per half
#define SITE_BYTES 32768     // 64*64*2 floats
#define PAIR_BYTES 65536     // 2 sites per TMA stage
#define STAGES 3             // 3 * 64KB ring = 192KB
#define WARPS 8              // warps per block, 1 chain each

typedef unsigned long long ull;

// Scratch (device globals — no allocation allowed)
__device__ __align__(16) float g_ct[HALFS * BOND * BOND * 2]; // right half, transposed+reversed
__device__ float g_vL[BATCH * BOND];
__device__ float g_wR[BATCH * BOND];

// ---- packed f32x2 helpers ----
static __device__ __forceinline__ ull ffma2(ull a, ull b, ull c) {
    ull d;
    asm("fma.rn.f32x2 %0, %1, %2, %3;" : "=l"(d) : "l"(a), "l"(b), "l"(c));
    return d;
}
static __device__ __forceinline__ ull fadd2(ull a, ull b) {
    ull d;
    asm("add.rn.f32x2 %0, %1, %2;" : "=l"(d) : "l"(a), "l"(b));
    return d;
}
static __device__ __forceinline__ float f2lo(ull v) {
    return __uint_as_float((unsigned)(v & 0xffffffffull));
}
static __device__ __forceinline__ float f2hi(ull v) {
    return __uint_as_float((unsigned)(v >> 32));
}
static __device__ __forceinline__ ull dup2(float v) {
    unsigned u = __float_as_uint(v);
    return ((ull)u << 32) | u;
}
static __device__ __forceinline__ unsigned smem_u32(const void* p) {
    return (unsigned)__cvta_generic_to_shared(p);
}

// ---- mbarrier / bulk-copy primitives ----
static __device__ __forceinline__ void mbar_init(unsigned addr, unsigned count) {
    asm volatile("mbarrier.init.shared.b64 [%0], %1;" :: "r"(addr), "r"(count) : "memory");
}
static __device__ __forceinline__ void mbar_expect_tx(unsigned addr, unsigned bytes) {
    asm volatile("mbarrier.arrive.expect_tx.shared.b64 _, [%0], %1;"
                 :: "r"(addr), "r"(bytes) : "memory");
}
static __device__ __forceinline__ void mbar_arrive(unsigned addr) {
    asm volatile("mbarrier.arrive.shared.b64 _, [%0];" :: "r"(addr) : "memory");
}
static __device__ __forceinline__ void mbar_wait(unsigned addr, unsigned parity) {
    asm volatile(
        "{\n\t"
        ".reg .pred P;\n\t"
        "WAIT_%=:\n\t"
        "mbarrier.try_wait.parity.acquire.cta.shared::cta.b64 P, [%0], %1, 0x989680;\n\t"
        "@P bra.uni DONE_%=;\n\t"
        "bra.uni WAIT_%=;\n\t"
        "DONE_%=:\n\t"
        "}"
        :: "r"(addr), "r"(parity) : "memory");
}
static __device__ __forceinline__ void bulk_g2s(unsigned dst, const void* src,
                                                unsigned bytes, unsigned mbar) {
    asm volatile(
        "cp.async.bulk.shared::cluster.global.mbarrier::complete_tx::bytes [%0], [%1], %2, [%3];"
        :: "r"(dst), "l"(src), "r"(bytes), "r"(mbar) : "memory");
}

// ============================================================
// Kernel 1: repack right-half cores only.
// g_ct[t][r][2l+i] = cores[255 - t][l][r][i]  (transpose, reverse order)
// ============================================================
__global__ void __launch_bounds__(256) repack_kernel(const float* __restrict__ cores) {
    int t = blockIdx.x;            // 0..127
    int s = 255 - t;
    __shared__ float2 sh[64 * 65];
    const float2* src = (const float2*)cores + (size_t)s * 4096; // [l*64 + r] -> (c0,c1)
    float2* dst = (float2*)g_ct + (size_t)t * 4096;              // [r*64 + l]
    for (int idx = threadIdx.x; idx < 4096; idx += blockDim.x) {
        int l = idx >> 6, r = idx & 63;
        sh[r * 65 + l] = src[idx];
    }
    __syncthreads();
    for (int idx = threadIdx.x; idx < 4096; idx += blockDim.x) {
        int r = idx >> 6, l = idx & 63;
        dst[idx] = sh[r * 65 + l];
    }
}

// ============================================================
// Kernel 2: vector chains. 8 warps/block, ONE chain per warp,
// 2 warps per SMSP (stall-filling). grid (16, 2) = 32 blocks.
// Chains are warp-private: state double-buffered per warp, one
// __syncwarp per site, NO cross-warp barrier in the site loop.
// Warps share the block's TMA tile ring (3 x 64KB stage-pairs):
//   full[stg]  (count 1): flipped by TMA complete_tx; all warps wait.
//   empty[stg] (count 8): each warp arrives after finishing a pair;
//   producer (tid 0) waits it before refilling the stage. Warps may
//   drift up to ~1 pair — no lockstep.
// ============================================================
__global__ void __launch_bounds__(32 * WARPS) chain_kernel(
    const float* __restrict__ x,      // [B][S][2]
    const float* __restrict__ cores,  // [S][l][r][2]
    const float* __restrict__ lvec,
    const float* __restrict__ rvec)
{
    extern __shared__ __align__(128) char dynsmem[];   // STAGES * 64KB
    __shared__ __align__(16) ull st[WARPS][2][64];     // per-warp state, (v,v) pairs
    __shared__ __align__(16) float2 sx[WARPS][HALFS];  // per-chain x, site order
    __shared__ __align__(8) ull full_store[STAGES];
    __shared__ __align__(8) ull empty_store[STAGES];

    const int tid  = threadIdx.x;
    const int w    = tid >> 5;
    const int lane = tid & 31;
    const int half = blockIdx.y;
    const int o0   = 2 * lane;

    unsigned fmb[STAGES], emb[STAGES];
    #pragma unroll
    for (int si = 0; si < STAGES; ++si) {
        fmb[si] = smem_u32(&full_store[si]);
        emb[si] = smem_u32(&empty_store[si]);
    }
    if (tid == 0) {
        #pragma unroll
        for (int si = 0; si < STAGES; ++si) {
            mbar_init(fmb[si], 1);
            mbar_init(emb[si], WARPS);
        }
    }

    // Stage per-chain x values (site order t).
    for (int i = tid; i < WARPS * HALFS; i += 32 * WARPS) {
        int c = i >> 7, t = i & 127;
        int batch = blockIdx.x * WARPS + c;
        int s = half ? (255 - t) : t;
        sx[c][t] = *(const float2*)(x + ((size_t)batch * SITES + s) * 2);
    }
    // Init per-warp state (buffer 0) + register copy.
    const float* bv = half ? rvec : lvec;
    float r0 = bv[o0], r1 = bv[o0 + 1];
    st[w][0][o0]     = dup2(r0);
    st[w][0][o0 + 1] = dup2(r1);

    __syncthreads();  // mbar init + state/x visible

    const char* gsrc = half ? (const char*)g_ct : (const char*)cores;

    // Prime the ring (pairs 0..2).
    if (tid == 0) {
        #pragma unroll
        for (int pr = 0; pr < STAGES; ++pr) {
            mbar_expect_tx(fmb[pr], PAIR_BYTES);
            bulk_g2s(smem_u32(dynsmem + (size_t)pr * PAIR_BYTES),
                     gsrc + (size_t)pr * PAIR_BYTES, PAIR_BYTES, fmb[pr]);
        }
    }

    for (int t = 0; t < HALFS; ++t) {
        const int pair = t >> 1;
        const int stg  = pair % STAGES;

        if ((t & 1) == 0) {
            // Producer: refill the stage that held pair-1 with pair+2.
            if (tid == 0 && pair >= 1 && pair + 2 < NPAIRS) {
                const int s2 = (pair + 2) % STAGES;
                mbar_wait(emb[s2], ((pair - 1) / STAGES) & 1);
                mbar_expect_tx(fmb[s2], PAIR_BYTES);
                bulk_g2s(smem_u32(dynsmem + (size_t)s2 * PAIR_BYTES),
                         gsrc + (size_t)(pair + 2) * PAIR_BYTES, PAIR_BYTES, fmb[s2]);
            }
            mbar_wait(fmb[stg], (pair / STAGES) & 1);
        }

        const int cur = t & 1;  // state read buffer; write buffer = cur^1
        const ulonglong2* tp =
            (const ulonglong2*)(dynsmem + (size_t)stg * PAIR_BYTES + (size_t)cur * SITE_BYTES)
            + lane;
        const ulonglong2* sS = (const ulonglong2*)&st[w][cur][0];

        ull a0 = 0, a1 = 0, a2 = 0, a3 = 0;
        #pragma unroll
        for (int jj = 0; jj < 32; ++jj) {
            ulonglong2 ca = tp[(2 * jj) * 32];       // row 2jj:  (c0,c1) for o0 | o0+1
            ulonglong2 cb = tp[(2 * jj + 1) * 32];   // row 2jj+1
            ulonglong2 vv = sS[jj];                  // (v,v)@2jj | (v,v)@2jj+1 (broadcast)
            a0 = ffma2(ca.x, vv.x, a0);
            a1 = ffma2(ca.y, vv.x, a1);
            a2 = ffma2(cb.x, vv.y, a2);
            a3 = ffma2(cb.y, vv.y, a3);
        }
        ull d0 = fadd2(a0, a2);   // (dot_f0, dot_f1) for output o0
        ull d1 = fadd2(a1, a3);   // for output o0+1

        const float2 xv = sx[w][t];
        r0 = fmaf(xv.x, f2lo(d0), fmaf(xv.y, f2hi(d0), r0));
        r1 = fmaf(xv.x, f2lo(d1), fmaf(xv.y, f2hi(d1), r1));

        *(ulonglong2*)&st[w][cur ^ 1][o0] = make_ulonglong2(dup2(r0), dup2(r1));
        __syncwarp();

        // End of a pair: this warp releases the stage.
        if ((t & 1) == 1 && lane == 0)
            mbar_arrive(emb[stg]);
    }

    // Final state is in registers.
    float* dst = half ? g_wR : g_vL;
    const int batch = blockIdx.x * WARPS + w;
    dst[batch * 64 + o0]     = r0;
    dst[batch * 64 + o0 + 1] = r1;
}

// ============================================================
// Kernel 3: logits[b][o] = sum_{l,r} vL[l] * oc[o][l][r] * wR[r]
// ============================================================
__global__ void __launch_bounds__(64) combine_kernel(
    const float* __restrict__ oc, float* __restrict__ out)
{
    const int b = blockIdx.x;
    const int tid = threadIdx.x; // 0..63 = r
    __shared__ float vL[64], wR[64];
    __shared__ float red[2];
    vL[tid] = g_vL[b * 64 + tid];
    wR[tid] = g_wR[b * 64 + tid];
    __syncthreads();
    const float w = wR[tid];
    for (int o = 0; o < NOUT; ++o) {
        float acc = 0.f;
        const float* row = oc + (size_t)o * 4096 + tid;
        #pragma unroll 16
        for (int l = 0; l < 64; ++l)
            acc = fmaf(vL[l], row[(size_t)l * 64], acc);
        float pv = acc * w;
        #pragma unroll
        for (int off = 16; off; off >>= 1)
            pv += __shfl_down_sync(0xffffffffu, pv, off);
        if ((tid & 31) == 0) red[tid >> 5] = pv;
        __syncthreads();
        if (tid == 0) out[b * NOUT + o] = red[0] + red[1];
        __syncthreads();
    }
}

extern "C" void kernel_launch(void* const* d_in, const int* in_sizes, int n_in,
                              void* d_out, int out_size) {
    const float* input_data = (const float*)d_in[0]; // [128,256,2]
    const float* cores      = (const float*)d_in[1]; // [256,64,64,2]
    const float* out_core   = (const float*)d_in[2]; // [10,64,64]
    const float* lvec       = (const float*)d_in[3]; // [64]
    const float* rvec       = (const float*)d_in[4]; // [64]
    float* out = (float*)d_out;                      // [128,10]

    cudaFuncSetAttribute(chain_kernel,
                         cudaFuncAttributeMaxDynamicSharedMemorySize,
                         STAGES * PAIR_BYTES);

    repack_kernel<<<HALFS, 256>>>(cores);
    chain_kernel<<<dim3(BATCH / WARPS, 2), 32 * WARPS, STAGES * PAIR_BYTES>>>(
        input_data, cores, lvec, rvec);
    combine_kernel<<<BATCH, 64>>>(out_core, out);
}

// round 10
// speedup vs baseline: 1.9749x; 1.9749x over previous
#include <cuda_runtime.h>

#define BATCH 128
#define SITES 256
#define BOND 64
#define NOUT 10
#define HALFS 128            // sites per half
#define NPAIRS 64            // site pairs per half
#define SITE_BYTES 32768     // 64*64*2 floats
#define PAIR_BYTES 65536     // 2 sites per TMA stage
#define STAGES 3             // 3 * 64KB ring = 192KB

typedef unsigned long long ull;

// Scratch (device globals — no allocation allowed)
__device__ __align__(16) float g_ct[HALFS * BOND * BOND * 2]; // right half, transposed+reversed
__device__ float g_vL[BATCH * BOND];
__device__ float g_wR[BATCH * BOND];

// ---- packed f32x2 helpers ----
static __device__ __forceinline__ ull ffma2(ull a, ull b, ull c) {
    ull d;
    asm("fma.rn.f32x2 %0, %1, %2, %3;" : "=l"(d) : "l"(a), "l"(b), "l"(c));
    return d;
}
static __device__ __forceinline__ ull fadd2(ull a, ull b) {
    ull d;
    asm("add.rn.f32x2 %0, %1, %2;" : "=l"(d) : "l"(a), "l"(b));
    return d;
}
static __device__ __forceinline__ float f2lo(ull v) {
    return __uint_as_float((unsigned)(v & 0xffffffffull));
}
static __device__ __forceinline__ float f2hi(ull v) {
    return __uint_as_float((unsigned)(v >> 32));
}
static __device__ __forceinline__ ull dup2(float v) {
    unsigned u = __float_as_uint(v);
    return ((ull)u << 32) | u;
}
static __device__ __forceinline__ unsigned smem_u32(const void* p) {
    return (unsigned)__cvta_generic_to_shared(p);
}

// ---- mbarrier / bulk-copy primitives ----
static __device__ __forceinline__ void mbar_init(unsigned addr, unsigned count) {
    asm volatile("mbarrier.init.shared.b64 [%0], %1;" :: "r"(addr), "r"(count) : "memory");
}
static __device__ __forceinline__ void mbar_expect_tx(unsigned addr, unsigned bytes) {
    asm volatile("mbarrier.arrive.expect_tx.shared.b64 _, [%0], %1;"
                 :: "r"(addr), "r"(bytes) : "memory");
}
static __device__ __forceinline__ void mbar_arrive(unsigned addr) {
    asm volatile("mbarrier.arrive.shared.b64 _, [%0];" :: "r"(addr) : "memory");
}
static __device__ __forceinline__ void mbar_wait(unsigned addr, unsigned parity) {
    asm volatile(
        "{\n\t"
        ".reg .pred P;\n\t"
        "WAIT_%=:\n\t"
        "mbarrier.try_wait.parity.acquire.cta.shared::cta.b64 P, [%0], %1, 0x989680;\n\t"
        "@P bra.uni DONE_%=;\n\t"
        "bra.uni WAIT_%=;\n\t"
        "DONE_%=:\n\t"
        "}"
        :: "r"(addr), "r"(parity) : "memory");
}
static __device__ __forceinline__ void bulk_g2s(unsigned dst, const void* src,
                                                unsigned bytes, unsigned mbar) {
    asm volatile(
        "cp.async.bulk.shared::cluster.global.mbarrier::complete_tx::bytes [%0], [%1], %2, [%3];"
        :: "r"(dst), "l"(src), "r"(bytes), "r"(mbar) : "memory");
}

// ============================================================
// Kernel 0: no-op — shifts ncu's -s 5 capture window so the chain
// kernel (not repack) lands in the profiled slot.
// ============================================================
__global__ void dummy_kernel() {}

// ============================================================
// Kernel 1: repack right-half cores only.
// g_ct[t][r][2l+i] = cores[255 - t][l][r][i]  (transpose, reverse order)
// ============================================================
__global__ void __launch_bounds__(256) repack_kernel(const float* __restrict__ cores) {
    int t = blockIdx.x;            // 0..127
    int s = 255 - t;
    __shared__ float2 sh[64 * 65];
    const float2* src = (const float2*)cores + (size_t)s * 4096; // [l*64 + r] -> (c0,c1)
    float2* dst = (float2*)g_ct + (size_t)t * 4096;              // [r*64 + l]
    for (int idx = threadIdx.x; idx < 4096; idx += blockDim.x) {
        int l = idx >> 6, r = idx & 63;
        sh[r * 65 + l] = src[idx];
    }
    __syncthreads();
    for (int idx = threadIdx.x; idx < 4096; idx += blockDim.x) {
        int r = idx >> 6, l = idx & 63;
        dst[idx] = sh[r * 65 + l];
    }
}

// ============================================================
// Kernel 2: vector chains. 2 warps/block, 2 chains/block, row-split:
// warp w computes partial dots over rows [32w, 32w+32), the two
// partials are combined through shared with two 64-thread barriers
// per site (halves each warp's serial path vs R7). grid (64,2) = 128
// blocks = 128 SMs. Private 3-stage x 2-site TMA ring per block.
// State double-buffered; warp w finalizes outputs [32w, 32w+32).
// ============================================================
__global__ void __launch_bounds__(64) chain_kernel(
    const float* __restrict__ x,      // [B][S][2]
    const float* __restrict__ cores,  // [S][l][r][2]
    const float* __restrict__ lvec,
    const float* __restrict__ rvec)
{
    extern __shared__ __align__(128) char dynsmem[];   // STAGES * 64KB
    __shared__ __align__(16) ull st[2][2][64];         // [buf][chain][j] = (v,v)
    __shared__ __align__(16) ull pp[2][2][64];         // [warp][chain][out] partial dot pairs
    __shared__ __align__(16) float2 sx[2][HALFS];      // per-chain x, site order
    __shared__ __align__(8) ull full_store[STAGES];
    __shared__ __align__(8) ull empty_store[STAGES];

    const int tid  = threadIdx.x;
    const int w    = tid >> 5;
    const int lane = tid & 31;
    const int half = blockIdx.y;

    unsigned fmb[STAGES], emb[STAGES];
    #pragma unroll
    for (int si = 0; si < STAGES; ++si) {
        fmb[si] = smem_u32(&full_store[si]);
        emb[si] = smem_u32(&empty_store[si]);
    }
    if (tid == 0) {
        #pragma unroll
        for (int si = 0; si < STAGES; ++si) {
            mbar_init(fmb[si], 1);
            mbar_init(emb[si], 2);          // one arrive per warp per pair
        }
    }

    // Stage per-chain x values (site order t).
    for (int i = tid; i < 2 * HALFS; i += 64) {
        int c = i >> 7, t = i & 127;
        int batch = blockIdx.x * 2 + c;
        int s = half ? (255 - t) : t;
        sx[c][t] = *(const float2*)(x + ((size_t)batch * SITES + s) * 2);
    }
    // Init state buffer 0 with the boundary vector.
    const float* bv = half ? rvec : lvec;
    for (int i = tid; i < 2 * 64; i += 64) {
        int c = i >> 6, j = i & 63;
        st[0][c][j] = dup2(bv[j]);
    }
    __syncthreads();

    const char* gsrc = half ? (const char*)g_ct : (const char*)cores;

    // Prime the ring (pairs 0..2).
    if (tid == 0) {
        #pragma unroll
        for (int pr = 0; pr < STAGES; ++pr) {
            mbar_expect_tx(fmb[pr], PAIR_BYTES);
            bulk_g2s(smem_u32(dynsmem + (size_t)pr * PAIR_BYTES),
                     gsrc + (size_t)pr * PAIR_BYTES, PAIR_BYTES, fmb[pr]);
        }
    }

    const int o = 32 * w + lane;   // output this thread finalizes

    for (int t = 0; t < HALFS; ++t) {
        const int pair = t >> 1;
        const int stg  = pair % STAGES;

        if ((t & 1) == 0) {
            // Producer: refill the stage that held pair-1 with pair+2.
            if (tid == 0 && pair >= 1 && pair + 2 < NPAIRS) {
                const int s2 = (pair + 2) % STAGES;
                mbar_wait(emb[s2], ((pair - 1) / STAGES) & 1);
                mbar_expect_tx(fmb[s2], PAIR_BYTES);
                bulk_g2s(smem_u32(dynsmem + (size_t)s2 * PAIR_BYTES),
                         gsrc + (size_t)(pair + 2) * PAIR_BYTES, PAIR_BYTES, fmb[s2]);
            }
            mbar_wait(fmb[stg], (pair / STAGES) & 1);
        }

        const int cur = t & 1;  // state read buffer; write buffer = cur^1
        const ulonglong2* tp =
            (const ulonglong2*)(dynsmem + (size_t)stg * PAIR_BYTES + (size_t)cur * SITE_BYTES)
            + lane;
        const ulonglong2* sA = (const ulonglong2*)&st[cur][0][0];
        const ulonglong2* sB = (const ulonglong2*)&st[cur][1][0];

        // Partial dot over rows [32w, 32w+32): lane accumulates for
        // outputs 2*lane, 2*lane+1 of both chains.
        ull a0 = 0, a1 = 0, a2 = 0, a3 = 0;   // chain A
        ull b0 = 0, b1 = 0, b2 = 0, b3 = 0;   // chain B
        #pragma unroll
        for (int q = 0; q < 16; ++q) {
            const int jj = 16 * w + q;
            ulonglong2 ca = tp[(2 * jj) * 32];       // row 2jj:  (c0,c1) for o0 | o0+1
            ulonglong2 cb = tp[(2 * jj + 1) * 32];   // row 2jj+1
            ulonglong2 vA = sA[jj];                  // (v,v)@2jj | (v,v)@2jj+1 (broadcast)
            ulonglong2 vB = sB[jj];
            a0 = ffma2(ca.x, vA.x, a0);
            a1 = ffma2(ca.y, vA.x, a1);
            a2 = ffma2(cb.x, vA.y, a2);
            a3 = ffma2(cb.y, vA.y, a3);
            b0 = ffma2(ca.x, vB.x, b0);
            b1 = ffma2(ca.y, vB.x, b1);
            b2 = ffma2(cb.x, vB.y, b2);
            b3 = ffma2(cb.y, vB.y, b3);
        }
        // pp[w][c][output] = (dot_f0, dot_f1) partial over this warp's rows
        *(ulonglong2*)&pp[w][0][2 * lane] =
            make_ulonglong2(fadd2(a0, a2), fadd2(a1, a3));
        *(ulonglong2*)&pp[w][1][2 * lane] =
            make_ulonglong2(fadd2(b0, b2), fadd2(b1, b3));

        __syncthreads();  // partials visible

        // Finalize output o for both chains.
        ull tA = fadd2(pp[0][0][o], pp[1][0][o]);
        ull tB = fadd2(pp[0][1][o], pp[1][1][o]);
        const float2 xA = sx[0][t];
        const float2 xB = sx[1][t];
        const float vAo = f2lo(st[cur][0][o]);
        const float vBo = f2lo(st[cur][1][o]);
        const float nA = fmaf(xA.x, f2lo(tA), fmaf(xA.y, f2hi(tA), vAo));
        const float nB = fmaf(xB.x, f2lo(tB), fmaf(xB.y, f2hi(tB), vBo));
        st[cur ^ 1][0][o] = dup2(nA);
        st[cur ^ 1][1][o] = dup2(nB);

        // End of a pair: each warp releases the stage (before the barrier,
        // so the producer's emb wait at the next even t is safe).
        if ((t & 1) == 1 && lane == 0)
            mbar_arrive(emb[stg]);

        __syncthreads();  // new state visible; stage fully consumed
    }

    // 128 sites -> final state in buffer 0.
    float* dst = half ? g_wR : g_vL;
    dst[(blockIdx.x * 2 + 0) * 64 + o] = f2lo(st[0][0][o]);
    dst[(blockIdx.x * 2 + 1) * 64 + o] = f2lo(st[0][1][o]);
}

// ============================================================
// Kernel 3: logits[b][o] = sum_{l,r} vL[l] * oc[o][l][r] * wR[r]
// ============================================================
__global__ void __launch_bounds__(64) combine_kernel(
    const float* __restrict__ oc, float* __restrict__ out)
{
    const int b = blockIdx.x;
    const int tid = threadIdx.x; // 0..63 = r
    __shared__ float vL[64], wR[64];
    __shared__ float red[2];
    vL[tid] = g_vL[b * 64 + tid];
    wR[tid] = g_wR[b * 64 + tid];
    __syncthreads();
    const float w = wR[tid];
    for (int o = 0; o < NOUT; ++o) {
        float acc = 0.f;
        const float* row = oc + (size_t)o * 4096 + tid;
        #pragma unroll 16
        for (int l = 0; l < 64; ++l)
            acc = fmaf(vL[l], row[(size_t)l * 64], acc);
        float pv = acc * w;
        #pragma unroll
        for (int off = 16; off; off >>= 1)
            pv += __shfl_down_sync(0xffffffffu, pv, off);
        if ((tid & 31) == 0) red[tid >> 5] = pv;
        __syncthreads();
        if (tid == 0) out[b * NOUT + o] = red[0] + red[1];
        __syncthreads();
    }
}

extern "C" void kernel_launch(void* const* d_in, const int* in_sizes, int n_in,
                              void* d_out, int out_size) {
    const float* input_data = (const float*)d_in[0]; // [128,256,2]
    const float* cores      = (const float*)d_in[1]; // [256,64,64,2]
    const float* out_core   = (const float*)d_in[2]; // [10,64,64]
    const float* lvec       = (const float*)d_in[3]; // [64]
    const float* rvec       = (const float*)d_in[4]; // [64]
    float* out = (float*)d_out;                      // [128,10]

    cudaFuncSetAttribute(chain_kernel,
                         cudaFuncAttributeMaxDynamicSharedMemorySize,
                         STAGES * PAIR_BYTES);

    // Two no-op launches shift ncu's skip-5 capture onto chain_kernel.
    dummy_kernel<<<1, 32>>>();
    dummy_kernel<<<1, 32>>>();
    repack_kernel<<<HALFS, 256>>>(cores);
    chain_kernel<<<dim3(64, 2), 64, STAGES * PAIR_BYTES>>>(input_data, cores, lvec, rvec);
    combine_kernel<<<BATCH, 64>>>(out_core, out);
}

// round 11
// speedup vs baseline: 1.9856x; 1.0054x over previous
#include <cuda_runtime.h>

#define BATCH 128
#define SITES 256
#define BOND 64
#define NOUT 10
#define HALFS 128            // sites per half
#define NPAIRS 64            // site pairs per half
#define SITE_BYTES 32768     // 64*64*2 floats
#define PAIR_BYTES 65536     // 2 sites per TMA stage
#define STAGES 3             // 3 * 64KB ring = 192KB

typedef unsigned long long ull;

// Scratch (device globals — no allocation allowed)
__device__ __align__(16) float g_ct[HALFS * BOND * BOND * 2]; // right half, transposed+reversed
__device__ float g_vL[BATCH * BOND];
__device__ float g_wR[BATCH * BOND];

// ---- packed f32x2 helpers ----
static __device__ __forceinline__ ull ffma2(ull a, ull b, ull c) {
    ull d;
    asm("fma.rn.f32x2 %0, %1, %2, %3;" : "=l"(d) : "l"(a), "l"(b), "l"(c));
    return d;
}
static __device__ __forceinline__ ull fadd2(ull a, ull b) {
    ull d;
    asm("add.rn.f32x2 %0, %1, %2;" : "=l"(d) : "l"(a), "l"(b));
    return d;
}
static __device__ __forceinline__ float f2lo(ull v) {
    return __uint_as_float((unsigned)(v & 0xffffffffull));
}
static __device__ __forceinline__ float f2hi(ull v) {
    return __uint_as_float((unsigned)(v >> 32));
}
static __device__ __forceinline__ ull dup2(float v) {
    unsigned u = __float_as_uint(v);
    return ((ull)u << 32) | u;
}
static __device__ __forceinline__ unsigned smem_u32(const void* p) {
    return (unsigned)__cvta_generic_to_shared(p);
}

// ---- mbarrier / bulk-copy primitives ----
static __device__ __forceinline__ void mbar_init(unsigned addr, unsigned count) {
    asm volatile("mbarrier.init.shared.b64 [%0], %1;" :: "r"(addr), "r"(count) : "memory");
}
static __device__ __forceinline__ void mbar_expect_tx(unsigned addr, unsigned bytes) {
    asm volatile("mbarrier.arrive.expect_tx.shared.b64 _, [%0], %1;"
                 :: "r"(addr), "r"(bytes) : "memory");
}
static __device__ __forceinline__ void mbar_arrive(unsigned addr) {
    asm volatile("mbarrier.arrive.shared.b64 _, [%0];" :: "r"(addr) : "memory");
}
static __device__ __forceinline__ void mbar_wait(unsigned addr, unsigned parity) {
    asm volatile(
        "{\n\t"
        ".reg .pred P;\n\t"
        "WAIT_%=:\n\t"
        "mbarrier.try_wait.parity.acquire.cta.shared::cta.b64 P, [%0], %1, 0x989680;\n\t"
        "@P bra.uni DONE_%=;\n\t"
        "bra.uni WAIT_%=;\n\t"
        "DONE_%=:\n\t"
        "}"
        :: "r"(addr), "r"(parity) : "memory");
}
static __device__ __forceinline__ void bulk_g2s(unsigned dst, const void* src,
                                                unsigned bytes, unsigned mbar) {
    asm volatile(
        "cp.async.bulk.shared::cluster.global.mbarrier::complete_tx::bytes [%0], [%1], %2, [%3];"
        :: "r"(dst), "l"(src), "r"(bytes), "r"(mbar) : "memory");
}

// ============================================================
// Kernel 0: no-op — keeps ncu's -s 5 capture window on chain_kernel.
// ============================================================
__global__ void dummy_kernel() {}

// ============================================================
// Kernel 1: repack right-half cores only.
// g_ct[t][r][2l+i] = cores[255 - t][l][r][i]  (transpose, reverse order)
// ============================================================
__global__ void __launch_bounds__(256) repack_kernel(const float* __restrict__ cores) {
    int t = blockIdx.x;            // 0..127
    int s = 255 - t;
    __shared__ float2 sh[64 * 65];
    const float2* src = (const float2*)cores + (size_t)s * 4096; // [l*64 + r] -> (c0,c1)
    float2* dst = (float2*)g_ct + (size_t)t * 4096;              // [r*64 + l]
    for (int idx = threadIdx.x; idx < 4096; idx += blockDim.x) {
        int l = idx >> 6, r = idx & 63;
        sh[r * 65 + l] = src[idx];
    }
    __syncthreads();
    for (int idx = threadIdx.x; idx < 4096; idx += blockDim.x) {
        int r = idx >> 6, l = idx & 63;
        dst[idx] = sh[r * 65 + l];
    }
}

// ============================================================
// Kernel 2: vector chains. 4 warps/block (one per SMSP), 2 chains,
// 4-way row split: warp w partial-dots rows [16w, 16w+16) for BOTH
// chains (tile values loaded once, used twice). Finalize is spread
// over all 128 threads: thread = (chain = tid>>6, output = tid&63).
// grid (64,2) = 128 blocks = 128 SMs. Private 3-stage x 2-site TMA
// ring; state double-buffered; 2 barriers per site.
// ============================================================
__global__ void __launch_bounds__(128) chain_kernel(
    const float* __restrict__ x,      // [B][S][2]
    const float* __restrict__ cores,  // [S][l][r][2]
    const float* __restrict__ lvec,
    const float* __restrict__ rvec)
{
    extern __shared__ __align__(128) char dynsmem[];   // STAGES * 64KB
    __shared__ __align__(16) ull st[2][2][64];         // [buf][chain][j] = (v,v)
    __shared__ __align__(16) ull pp[4][2][64];         // [warp][chain][out] partial dot pairs
    __shared__ __align__(16) float2 sx[2][HALFS];      // per-chain x, site order
    __shared__ __align__(8) ull full_store[STAGES];
    __shared__ __align__(8) ull empty_store[STAGES];

    const int tid  = threadIdx.x;
    const int w    = tid >> 5;
    const int lane = tid & 31;
    const int half = blockIdx.y;
    const int fc   = tid >> 6;      // chain this thread finalizes
    const int fo   = tid & 63;      // output this thread finalizes

    unsigned fmb[STAGES], emb[STAGES];
    #pragma unroll
    for (int si = 0; si < STAGES; ++si) {
        fmb[si] = smem_u32(&full_store[si]);
        emb[si] = smem_u32(&empty_store[si]);
    }
    if (tid == 0) {
        #pragma unroll
        for (int si = 0; si < STAGES; ++si) {
            mbar_init(fmb[si], 1);
            mbar_init(emb[si], 1);          // single release per pair
        }
    }

    // Stage per-chain x values (site order t).
    for (int i = tid; i < 2 * HALFS; i += 128) {
        int c = i >> 7, t = i & 127;
        int batch = blockIdx.x * 2 + c;
        int s = half ? (255 - t) : t;
        sx[c][t] = *(const float2*)(x + ((size_t)batch * SITES + s) * 2);
    }
    // Init state buffer 0 with the boundary vector.
    const float* bv = half ? rvec : lvec;
    if (tid < 128) {
        st[0][fc][fo] = dup2(bv[fo]);
    }
    __syncthreads();

    const char* gsrc = half ? (const char*)g_ct : (const char*)cores;

    // Prime the ring (pairs 0..2).
    if (tid == 0) {
        #pragma unroll
        for (int pr = 0; pr < STAGES; ++pr) {
            mbar_expect_tx(fmb[pr], PAIR_BYTES);
            bulk_g2s(smem_u32(dynsmem + (size_t)pr * PAIR_BYTES),
                     gsrc + (size_t)pr * PAIR_BYTES, PAIR_BYTES, fmb[pr]);
        }
    }

    for (int t = 0; t < HALFS; ++t) {
        const int pair = t >> 1;
        const int stg  = pair % STAGES;

        if ((t & 1) == 0) {
            // Producer: refill the stage that held pair-1 with pair+2.
            if (tid == 0 && pair >= 1 && pair + 2 < NPAIRS) {
                const int s2 = (pair + 2) % STAGES;
                mbar_wait(emb[s2], ((pair - 1) / STAGES) & 1);
                mbar_expect_tx(fmb[s2], PAIR_BYTES);
                bulk_g2s(smem_u32(dynsmem + (size_t)s2 * PAIR_BYTES),
                         gsrc + (size_t)(pair + 2) * PAIR_BYTES, PAIR_BYTES, fmb[s2]);
            }
            mbar_wait(fmb[stg], (pair / STAGES) & 1);
        }

        const int cur = t & 1;  // state read buffer; write buffer = cur^1
        const ulonglong2* tp =
            (const ulonglong2*)(dynsmem + (size_t)stg * PAIR_BYTES + (size_t)cur * SITE_BYTES)
            + lane;
        const ulonglong2* sA = (const ulonglong2*)&st[cur][0][0];
        const ulonglong2* sB = (const ulonglong2*)&st[cur][1][0];

        // Partial dot over rows [16w, 16w+16): lane accumulates for
        // outputs 2*lane, 2*lane+1 of both chains.
        ull a0 = 0, a1 = 0, a2 = 0, a3 = 0;   // chain A
        ull b0 = 0, b1 = 0, b2 = 0, b3 = 0;   // chain B
        #pragma unroll
        for (int q = 0; q < 8; ++q) {
            const int jj = 8 * w + q;
            ulonglong2 ca = tp[(2 * jj) * 32];       // row 2jj:  (c0,c1) for o0 | o0+1
            ulonglong2 cb = tp[(2 * jj + 1) * 32];   // row 2jj+1
            ulonglong2 vA = sA[jj];                  // (v,v)@2jj | (v,v)@2jj+1 (broadcast)
            ulonglong2 vB = sB[jj];
            a0 = ffma2(ca.x, vA.x, a0);
            a1 = ffma2(ca.y, vA.x, a1);
            a2 = ffma2(cb.x, vA.y, a2);
            a3 = ffma2(cb.y, vA.y, a3);
            b0 = ffma2(ca.x, vB.x, b0);
            b1 = ffma2(ca.y, vB.x, b1);
            b2 = ffma2(cb.x, vB.y, b2);
            b3 = ffma2(cb.y, vB.y, b3);
        }
        // pp[w][c][output] = (dot_f0, dot_f1) partial over this warp's rows
        *(ulonglong2*)&pp[w][0][2 * lane] =
            make_ulonglong2(fadd2(a0, a2), fadd2(a1, a3));
        *(ulonglong2*)&pp[w][1][2 * lane] =
            make_ulonglong2(fadd2(b0, b2), fadd2(b1, b3));

        __syncthreads();  // partials visible; all tile reads for this site done

        // Release the stage after its second site is consumed.
        if ((t & 1) == 1 && tid == 0)
            mbar_arrive(emb[stg]);

        // Finalize: thread handles (fc, fo).
        ull sum = fadd2(fadd2(pp[0][fc][fo], pp[1][fc][fo]),
                        fadd2(pp[2][fc][fo], pp[3][fc][fo]));
        const float2 xv = sx[fc][t];
        const float vo = f2lo(st[cur][fc][fo]);
        const float nv = fmaf(xv.x, f2lo(sum), fmaf(xv.y, f2hi(sum), vo));
        st[cur ^ 1][fc][fo] = dup2(nv);

        __syncthreads();  // new state visible before next site's dot reads
    }

    // 128 sites -> final state in buffer 0.
    float* dst = half ? g_wR : g_vL;
    dst[(blockIdx.x * 2 + fc) * 64 + fo] = f2lo(st[0][fc][fo]);
}

// ============================================================
// Kernel 3: logits[b][o] = sum_{l,r} vL[l] * oc[o][l][r] * wR[r]
// ============================================================
__global__ void __launch_bounds__(64) combine_kernel(
    const float* __restrict__ oc, float* __restrict__ out)
{
    const int b = blockIdx.x;
    const int tid = threadIdx.x; // 0..63 = r
    __shared__ float vL[64], wR[64];
    __shared__ float red[2];
    vL[tid] = g_vL[b * 64 + tid];
    wR[tid] = g_wR[b * 64 + tid];
    __syncthreads();
    const float w = wR[tid];
    for (int o = 0; o < NOUT; ++o) {
        float acc = 0.f;
        const float* row = oc + (size_t)o * 4096 + tid;
        #pragma unroll 16
        for (int l = 0; l < 64; ++l)
            acc = fmaf(vL[l], row[(size_t)l * 64], acc);
        float pv = acc * w;
        #pragma unroll
        for (int off = 16; off; off >>= 1)
            pv += __shfl_down_sync(0xffffffffu, pv, off);
        if ((tid & 31) == 0) red[tid >> 5] = pv;
        __syncthreads();
        if (tid == 0) out[b * NOUT + o] = red[0] + red[1];
        __syncthreads();
    }
}

extern "C" void kernel_launch(void* const* d_in, const int* in_sizes, int n_in,
                              void* d_out, int out_size) {
    const float* input_data = (const float*)d_in[0]; // [128,256,2]
    const float* cores      = (const float*)d_in[1]; // [256,64,64,2]
    const float* out_core   = (const float*)d_in[2]; // [10,64,64]
    const float* lvec       = (const float*)d_in[3]; // [64]
    const float* rvec       = (const float*)d_in[4]; // [64]
    float* out = (float*)d_out;                      // [128,10]

    cudaFuncSetAttribute(chain_kernel,
                         cudaFuncAttributeMaxDynamicSharedMemorySize,
                         STAGES * PAIR_BYTES);

    // Two no-op launches keep ncu's skip-5 capture on chain_kernel.
    dummy_kernel<<<1, 32>>>();
    dummy_kernel<<<1, 32>>>();
    repack_kernel<<<HALFS, 256>>>(cores);
    chain_kernel<<<dim3(64, 2), 128, STAGES * PAIR_BYTES>>>(input_data, cores, lvec, rvec);
    combine_kernel<<<BATCH, 64>>>(out_core, out);
}